// round 10
// baseline (speedup 1.0000x reference)
#include <cuda_runtime.h>

// SSN superpixel EM, sparse 9-neighborhood formulation.
// B=4, H=W=256, C=20, 16x16 superpixel grid, cell=16x16, K=256, 10 EM iters.

#define BN     4
#define HH     256
#define NN     (HH*HH)      // 65536 pixels
#define CC     20
#define KGRID  16
#define KK     (KGRID*KGRID)
#define CELLSZ 16
#define FPAD   24           // f_s row pad (words): [pix][24], c=20 -> 1.0, 21..23 -> 0

// Scratch (device globals: no allocation allowed)
__device__ float g_mean[BN * KK * CC];
__device__ float g_partA[BN * KK * 9 * 21];
__device__ float g_partB[BN * KK * 9 * 21];

// ---------------------------------------------------------------------------
// INIT: mean of features within each initial 16x16 cell. grid=(K,B), 256 thr.
// ---------------------------------------------------------------------------
__global__ __launch_bounds__(256) void ssn_init_mean(const float* __restrict__ feat) {
    const int b = blockIdx.y, cell = blockIdx.x, t = threadIdx.x;
    const int py = cell >> 4, px = cell & 15;
    const int r = t >> 4, cc = t & 15;
    const int n = (py * CELLSZ + r) * HH + px * CELLSZ + cc;

    const float4* fp = reinterpret_cast<const float4*>(feat + (size_t)(b * NN + n) * CC);
    float f[CC];
    {
        float4 v;
        v = fp[0]; f[0]=v.x; f[1]=v.y; f[2]=v.z; f[3]=v.w;
        v = fp[1]; f[4]=v.x; f[5]=v.y; f[6]=v.z; f[7]=v.w;
        v = fp[2]; f[8]=v.x; f[9]=v.y; f[10]=v.z; f[11]=v.w;
        v = fp[3]; f[12]=v.x; f[13]=v.y; f[14]=v.z; f[15]=v.w;
        v = fp[4]; f[16]=v.x; f[17]=v.y; f[18]=v.z; f[19]=v.w;
    }

    __shared__ float ssum[CC];
    if (t < CC) ssum[t] = 0.0f;
    __syncthreads();

    const int lane = t & 31;
    #pragma unroll
    for (int c = 0; c < CC; ++c) {
        float v = f[c];
        #pragma unroll
        for (int off = 16; off > 0; off >>= 1)
            v += __shfl_xor_sync(0xffffffffu, v, off);
        if (lane == 0) atomicAdd(&ssum[c], v);
    }
    __syncthreads();
    if (t < CC) g_mean[(b * KK + cell) * CC + t] = ssum[t] * (1.0f / 256.0f);
}

// ---------------------------------------------------------------------------
// EM iteration (fused mean-finalize + E-step + tiled/vectorized M-step).
// mode: 0 = read g_mean, write g_partA
//       1 = read g_partA, write g_partB
//       2 = read g_partB, write g_partA
// grid=(K,B) blocks of 256 (block = one 16x16 cell of one batch).
// ---------------------------------------------------------------------------
__global__ __launch_bounds__(256, 5) void ssn_em_iter(const float* __restrict__ feat, int mode) {
    __shared__ __align__(16) float f_s[256 * FPAD];     // [pix][24]: f[0..19], 1.0, 0,0,0
    __shared__ __align__(16) float p_s[3 * 256 * 4];    // [jt][pix][4]: p[3jt..3jt+2], 0
    __shared__ __align__(16) float mean_s[9 * CC];      // float4-read (rows 80B)
    __shared__ float msq_s[9];
    __shared__ float raw_s[9 * 21 + 3];

    const int b = blockIdx.y, cell = blockIdx.x, t = threadIdx.x;
    const int py = cell >> 4, px = cell & 15;

    // -------- prologue: assemble the 9 neighbor-superpixel means --------
    if (mode == 0) {
        if (t < 9 * CC) {
            const int j = t / CC, c = t % CC;
            const int ky = py + j / 3 - 1, kx = px + j % 3 - 1;
            float m = 0.0f;
            if (ky >= 0 && ky < KGRID && kx >= 0 && kx < KGRID)
                m = g_mean[(b * KK + ky * KGRID + kx) * CC + c];
            mean_s[t] = m;
        }
    } else {
        const float* __restrict__ src = (mode == 1) ? g_partA : g_partB;
        if (t < 9 * 21) {
            const int j = t / 21, c = t % 21;
            const int ky = py + j / 3 - 1, kx = px + j % 3 - 1;
            float s = 0.0f;
            if (ky >= 0 && ky < KGRID && kx >= 0 && kx < KGRID) {
                #pragma unroll
                for (int dy = -1; dy <= 1; ++dy)
                    #pragma unroll
                    for (int dx = -1; dx <= 1; ++dx) {
                        const int cy = ky + dy, cx = kx + dx;
                        if (cy >= 0 && cy < KGRID && cx >= 0 && cx < KGRID) {
                            const int jj = (ky - cy + 1) * 3 + (kx - cx + 1);
                            s += src[((b * KK + cy * KGRID + cx) * 9 + jj) * 21 + c];
                        }
                    }
            }
            raw_s[t] = s;
        }
        __syncthreads();
        if (t < 9 * CC) {
            const int j = t / CC, c = t % CC;
            mean_s[t] = raw_s[j * 21 + c] / fmaxf(raw_s[j * 21 + 20], 1e-12f);
        }
    }
    __syncthreads();
    if (t < 9) {
        float s = 0.0f;
        #pragma unroll
        for (int c = 0; c < CC; ++c) { const float m = mean_s[t * CC + c]; s += m * m; }
        msq_s[t] = s;
    }
    __syncthreads();

    // -------- E-step: one pixel per thread --------
    // softmax(-dist) invariant to ||f||^2: p[j] ∝ exp(2*dot_j - msq_j).
    const int r = t >> 4, cc2 = t & 15;
    const int n = (py * CELLSZ + r) * HH + px * CELLSZ + cc2;
    const float4* fp = reinterpret_cast<const float4*>(feat + (size_t)(b * NN + n) * CC);
    float4 fv0 = fp[0], fv1 = fp[1], fv2 = fp[2], fv3 = fp[3], fv4 = fp[4];

    float s[9];
    float smax = -1e30f;
    #pragma unroll
    for (int j = 0; j < 9; ++j) {
        const int ky = py + j / 3 - 1, kx = px + j % 3 - 1;
        if (ky >= 0 && ky < KGRID && kx >= 0 && kx < KGRID) {
            const float4* mr = reinterpret_cast<const float4*>(mean_s + j * CC);
            float dot = 0.0f;
            float4 m;
            m = mr[0]; dot = fmaf(fv0.x,m.x,fmaf(fv0.y,m.y,fmaf(fv0.z,m.z,fmaf(fv0.w,m.w,dot))));
            m = mr[1]; dot = fmaf(fv1.x,m.x,fmaf(fv1.y,m.y,fmaf(fv1.z,m.z,fmaf(fv1.w,m.w,dot))));
            m = mr[2]; dot = fmaf(fv2.x,m.x,fmaf(fv2.y,m.y,fmaf(fv2.z,m.z,fmaf(fv2.w,m.w,dot))));
            m = mr[3]; dot = fmaf(fv3.x,m.x,fmaf(fv3.y,m.y,fmaf(fv3.z,m.z,fmaf(fv3.w,m.w,dot))));
            m = mr[4]; dot = fmaf(fv4.x,m.x,fmaf(fv4.y,m.y,fmaf(fv4.z,m.z,fmaf(fv4.w,m.w,dot))));
            s[j] = 2.0f * dot - msq_s[j];
            smax = fmaxf(smax, s[j]);
        } else {
            s[j] = -1e30f;
        }
    }
    float p[9], denom = 0.0f;
    #pragma unroll
    for (int j = 0; j < 9; ++j) {
        p[j] = (s[j] > -1e29f) ? __expf(s[j] - smax) : 0.0f;
        denom += p[j];
    }
    const float inv = 1.0f / denom;   // denom >= 1 (argmax contributes exp(0)=1)
    #pragma unroll
    for (int j = 0; j < 9; ++j) p[j] *= inv;

    // store p: 3 float4 rows [jt][pix][4]
    {
        float4* pr = reinterpret_cast<float4*>(p_s);
        pr[0 * 256 + t] = make_float4(p[0], p[1], p[2], 0.0f);
        pr[1 * 256 + t] = make_float4(p[3], p[4], p[5], 0.0f);
        pr[2 * 256 + t] = make_float4(p[6], p[7], p[8], 0.0f);
    }
    // store f row: 5 float4 + constant tail {1,0,0,0}
    {
        float4* fr = reinterpret_cast<float4*>(f_s + t * FPAD);
        fr[0] = fv0; fr[1] = fv1; fr[2] = fv2; fr[3] = fv3; fr[4] = fv4;
        fr[5] = make_float4(1.0f, 0.0f, 0.0f, 0.0f);
    }
    __syncthreads();

    // -------- M-step (tiled, vectorized): 9 tiles of (3j x 8c), 16 groups.
    // Thread (tile, g) accumulates 24 outputs over 16 pixels (3 LDS.128/pixel),
    // then a 4-stage half-warp butterfly reduces the 16 groups.
    float* __restrict__ dst = (mode == 1) ? g_partB : g_partA;
    if (t < 160) {
        const int tile = (t < 144) ? (t >> 4) : 8;  // lanes 16..31 of warp 4 duplicate tile 8
        const int g = t & 15;
        const int jt = tile / 3;                    // j-tile: rows 3*jt .. 3*jt+2
        const int c0 = (tile % 3) * 8;              // c-tile: cols c0 .. c0+7

        float acc[24];
        #pragma unroll
        for (int o = 0; o < 24; ++o) acc[o] = 0.0f;

        const float4* pbase = reinterpret_cast<const float4*>(p_s) + jt * 256;
        #pragma unroll 4
        for (int ii = 0; ii < 16; ++ii) {
            const int pix = ii * 16 + g;
            const float4 pv = pbase[pix];
            const float4* fr = reinterpret_cast<const float4*>(f_s + pix * FPAD + c0);
            const float4 fa = fr[0];
            const float4 fb = fr[1];
            acc[0]  = fmaf(pv.x, fa.x, acc[0]);
            acc[1]  = fmaf(pv.x, fa.y, acc[1]);
            acc[2]  = fmaf(pv.x, fa.z, acc[2]);
            acc[3]  = fmaf(pv.x, fa.w, acc[3]);
            acc[4]  = fmaf(pv.x, fb.x, acc[4]);
            acc[5]  = fmaf(pv.x, fb.y, acc[5]);
            acc[6]  = fmaf(pv.x, fb.z, acc[6]);
            acc[7]  = fmaf(pv.x, fb.w, acc[7]);
            acc[8]  = fmaf(pv.y, fa.x, acc[8]);
            acc[9]  = fmaf(pv.y, fa.y, acc[9]);
            acc[10] = fmaf(pv.y, fa.z, acc[10]);
            acc[11] = fmaf(pv.y, fa.w, acc[11]);
            acc[12] = fmaf(pv.y, fb.x, acc[12]);
            acc[13] = fmaf(pv.y, fb.y, acc[13]);
            acc[14] = fmaf(pv.y, fb.z, acc[14]);
            acc[15] = fmaf(pv.y, fb.w, acc[15]);
            acc[16] = fmaf(pv.z, fa.x, acc[16]);
            acc[17] = fmaf(pv.z, fa.y, acc[17]);
            acc[18] = fmaf(pv.z, fa.z, acc[18]);
            acc[19] = fmaf(pv.z, fa.w, acc[19]);
            acc[20] = fmaf(pv.z, fb.x, acc[20]);
            acc[21] = fmaf(pv.z, fb.y, acc[21]);
            acc[22] = fmaf(pv.z, fb.z, acc[22]);
            acc[23] = fmaf(pv.z, fb.w, acc[23]);
        }
        #pragma unroll
        for (int o = 0; o < 24; ++o) {
            #pragma unroll
            for (int off = 8; off >= 1; off >>= 1)
                acc[o] += __shfl_xor_sync(0xffffffffu, acc[o], off);
        }
        if (t < 144) {
            const int base = ((b * KK + cell) * 9 + 3 * jt) * 21 + c0;
            {   // output o = g (0..15): jj = g>>3, cc = g&7
                const int jj = g >> 3, cc = g & 7;
                if (c0 + cc <= 20) dst[base + jj * 21 + cc] = acc[g];
            }
            if (g < 8) {  // output o = 16+g: jj = 2, cc = g
                if (c0 + g <= 20) dst[base + 2 * 21 + g] = acc[16 + g];
            }
        }
    }
}

// ---------------------------------------------------------------------------
// FINAL: finalize mean from g_partA, E-step, expand to dense [B,N,K] output.
// grid=(K,B), 256 threads.
// ---------------------------------------------------------------------------
__global__ __launch_bounds__(256) void ssn_final(const float* __restrict__ feat,
                                                 float* __restrict__ out) {
    __shared__ float p_s[256 * 9];                      // p_s[pix][j]
    __shared__ __align__(16) float mean_s[9 * CC];
    __shared__ float msq_s[9];
    __shared__ float raw_s[9 * 21 + 3];

    const int b = blockIdx.y, cell = blockIdx.x, t = threadIdx.x;
    const int py = cell >> 4, px = cell & 15;

    // mean finalize from g_partA
    if (t < 9 * 21) {
        const int j = t / 21, c = t % 21;
        const int ky = py + j / 3 - 1, kx = px + j % 3 - 1;
        float s = 0.0f;
        if (ky >= 0 && ky < KGRID && kx >= 0 && kx < KGRID) {
            #pragma unroll
            for (int dy = -1; dy <= 1; ++dy)
                #pragma unroll
                for (int dx = -1; dx <= 1; ++dx) {
                    const int cy = ky + dy, cx = kx + dx;
                    if (cy >= 0 && cy < KGRID && cx >= 0 && cx < KGRID) {
                        const int jj = (ky - cy + 1) * 3 + (kx - cx + 1);
                        s += g_partA[((b * KK + cy * KGRID + cx) * 9 + jj) * 21 + c];
                    }
                }
        }
        raw_s[t] = s;
    }
    __syncthreads();
    if (t < 9 * CC) {
        const int j = t / CC, c = t % CC;
        mean_s[t] = raw_s[j * 21 + c] / fmaxf(raw_s[j * 21 + 20], 1e-12f);
    }
    __syncthreads();
    if (t < 9) {
        float s = 0.0f;
        #pragma unroll
        for (int c = 0; c < CC; ++c) { const float m = mean_s[t * CC + c]; s += m * m; }
        msq_s[t] = s;
    }
    __syncthreads();

    // E-step for this thread's pixel
    const int r = t >> 4, cc2 = t & 15;
    const int n = (py * CELLSZ + r) * HH + px * CELLSZ + cc2;
    const float4* fp = reinterpret_cast<const float4*>(feat + (size_t)(b * NN + n) * CC);
    float4 fv0 = fp[0], fv1 = fp[1], fv2 = fp[2], fv3 = fp[3], fv4 = fp[4];

    float s[9];
    float smax = -1e30f;
    #pragma unroll
    for (int j = 0; j < 9; ++j) {
        const int ky = py + j / 3 - 1, kx = px + j % 3 - 1;
        if (ky >= 0 && ky < KGRID && kx >= 0 && kx < KGRID) {
            const float4* mr = reinterpret_cast<const float4*>(mean_s + j * CC);
            float dot = 0.0f;
            float4 m;
            m = mr[0]; dot = fmaf(fv0.x,m.x,fmaf(fv0.y,m.y,fmaf(fv0.z,m.z,fmaf(fv0.w,m.w,dot))));
            m = mr[1]; dot = fmaf(fv1.x,m.x,fmaf(fv1.y,m.y,fmaf(fv1.z,m.z,fmaf(fv1.w,m.w,dot))));
            m = mr[2]; dot = fmaf(fv2.x,m.x,fmaf(fv2.y,m.y,fmaf(fv2.z,m.z,fmaf(fv2.w,m.w,dot))));
            m = mr[3]; dot = fmaf(fv3.x,m.x,fmaf(fv3.y,m.y,fmaf(fv3.z,m.z,fmaf(fv3.w,m.w,dot))));
            m = mr[4]; dot = fmaf(fv4.x,m.x,fmaf(fv4.y,m.y,fmaf(fv4.z,m.z,fmaf(fv4.w,m.w,dot))));
            s[j] = 2.0f * dot - msq_s[j];
            smax = fmaxf(smax, s[j]);
        } else {
            s[j] = -1e30f;
        }
    }
    float p[9], denom = 0.0f;
    #pragma unroll
    for (int j = 0; j < 9; ++j) {
        p[j] = (s[j] > -1e29f) ? __expf(s[j] - smax) : 0.0f;
        denom += p[j];
    }
    const float inv = 1.0f / denom;
    #pragma unroll
    for (int j = 0; j < 9; ++j) p_s[t * 9 + j] = p[j] * inv;
    __syncthreads();

    // Dense expansion: 64 iterations x (4 pixels x 64 float4s) = 256 pixels x 256 k
    const int sub = t >> 6;        // which of the 4 pixels this thread serves
    const int kq  = t & 63;        // float4 index within the k-row
    const int k0  = kq * 4;
    const int gy  = k0 >> 4;       // constant across the float4 (k0 % 16 <= 12)
    const int dy  = gy - py;
    const bool rowok = (dy >= -1 && dy <= 1);
    const int jbase = (dy + 1) * 3;
    const int gx0 = k0 & 15;

    for (int it = 0; it < 64; ++it) {
        const int pix = it * 4 + sub;
        const int rr = pix >> 4, cpx = pix & 15;
        const int n2 = (py * CELLSZ + rr) * HH + px * CELLSZ + cpx;
        const float* pr = &p_s[pix * 9];
        float4 v;
        {
            const int dx = gx0 + 0 - px;
            v.x = (rowok && dx >= -1 && dx <= 1) ? pr[jbase + dx + 1] : 0.0f;
        }
        {
            const int dx = gx0 + 1 - px;
            v.y = (rowok && dx >= -1 && dx <= 1) ? pr[jbase + dx + 1] : 0.0f;
        }
        {
            const int dx = gx0 + 2 - px;
            v.z = (rowok && dx >= -1 && dx <= 1) ? pr[jbase + dx + 1] : 0.0f;
        }
        {
            const int dx = gx0 + 3 - px;
            v.w = (rowok && dx >= -1 && dx <= 1) ? pr[jbase + dx + 1] : 0.0f;
        }
        reinterpret_cast<float4*>(out + (size_t)(b * NN + n2) * KK)[kq] = v;
    }
}

// ---------------------------------------------------------------------------
extern "C" void kernel_launch(void* const* d_in, const int* in_sizes, int n_in,
                              void* d_out, int out_size) {
    const float* feat = (const float*)d_in[0];
    float* out = (float*)d_out;
    (void)in_sizes; (void)n_in; (void)out_size;

    dim3 grid(KK, BN);

    ssn_init_mean<<<grid, 256>>>(feat);
    ssn_em_iter<<<grid, 256>>>(feat, 0);
    for (int i = 0; i < 4; ++i) {
        ssn_em_iter<<<grid, 256>>>(feat, 1);
        ssn_em_iter<<<grid, 256>>>(feat, 2);
    }
    ssn_final<<<grid, 256>>>(feat, out);
}

// round 11
// speedup vs baseline: 1.2034x; 1.2034x over previous
#include <cuda_runtime.h>

// SSN superpixel EM, sparse 9-neighborhood formulation.
// B=4, H=W=256, C=20, 16x16 superpixel grid, cell=16x16, K=256, 10 EM iters.

#define BN     4
#define HH     256
#define NN     (HH*HH)      // 65536 pixels
#define CC     20
#define KGRID  16
#define KK     (KGRID*KGRID)
#define CELLSZ 16
#define PS     258          // even smem stride: float2-aligned rows, conflict-free stride-1 access

// Scratch (device globals: no allocation allowed)
__device__ float g_mean[BN * KK * CC];
__device__ float g_partA[BN * KK * 9 * 21];
__device__ float g_partB[BN * KK * 9 * 21];

// ---------------------------------------------------------------------------
// INIT: mean of features within each initial 16x16 cell. grid=(K,B), 256 thr.
// ---------------------------------------------------------------------------
__global__ __launch_bounds__(256) void ssn_init_mean(const float* __restrict__ feat) {
    const int b = blockIdx.y, cell = blockIdx.x, t = threadIdx.x;
    const int py = cell >> 4, px = cell & 15;
    const int r = t >> 4, cc = t & 15;
    const int n = (py * CELLSZ + r) * HH + px * CELLSZ + cc;

    const float4* fp = reinterpret_cast<const float4*>(feat + (size_t)(b * NN + n) * CC);
    float f[CC];
    {
        float4 v;
        v = fp[0]; f[0]=v.x; f[1]=v.y; f[2]=v.z; f[3]=v.w;
        v = fp[1]; f[4]=v.x; f[5]=v.y; f[6]=v.z; f[7]=v.w;
        v = fp[2]; f[8]=v.x; f[9]=v.y; f[10]=v.z; f[11]=v.w;
        v = fp[3]; f[12]=v.x; f[13]=v.y; f[14]=v.z; f[15]=v.w;
        v = fp[4]; f[16]=v.x; f[17]=v.y; f[18]=v.z; f[19]=v.w;
    }

    __shared__ float ssum[CC];
    if (t < CC) ssum[t] = 0.0f;
    __syncthreads();

    const int lane = t & 31;
    #pragma unroll
    for (int c = 0; c < CC; ++c) {
        float v = f[c];
        #pragma unroll
        for (int off = 16; off > 0; off >>= 1)
            v += __shfl_xor_sync(0xffffffffu, v, off);
        if (lane == 0) atomicAdd(&ssum[c], v);
    }
    __syncthreads();
    if (t < CC) g_mean[(b * KK + cell) * CC + t] = ssum[t] * (1.0f / 256.0f);
}

// ---------------------------------------------------------------------------
// EM iteration (fused mean-finalize + E-step + tiled M-step, float2-paired).
// mode: 0 = read g_mean, write g_partA
//       1 = read g_partA, write g_partB
//       2 = read g_partB, write g_partA
// grid=(K,B) blocks of 256 (block = one 16x16 cell of one batch).
// ---------------------------------------------------------------------------
__global__ __launch_bounds__(256, 5) void ssn_em_iter(const float* __restrict__ feat, int mode) {
    __shared__ __align__(16) float p_s[9 * PS];         // p_s[j][pix]
    __shared__ __align__(16) float f_s[CC * PS];        // f_s[c][pix]
    __shared__ __align__(16) float mean_s[9 * CC];      // float4-read (rows 80B)
    __shared__ float msq_s[9];
    __shared__ float raw_s[9 * 21 + 3];

    const int b = blockIdx.y, cell = blockIdx.x, t = threadIdx.x;
    const int py = cell >> 4, px = cell & 15;

    // -------- prologue: assemble the 9 neighbor-superpixel means --------
    if (mode == 0) {
        if (t < 9 * CC) {
            const int j = t / CC, c = t % CC;
            const int ky = py + j / 3 - 1, kx = px + j % 3 - 1;
            float m = 0.0f;
            if (ky >= 0 && ky < KGRID && kx >= 0 && kx < KGRID)
                m = g_mean[(b * KK + ky * KGRID + kx) * CC + c];
            mean_s[t] = m;
        }
    } else {
        const float* __restrict__ src = (mode == 1) ? g_partA : g_partB;
        if (t < 9 * 21) {
            const int j = t / 21, c = t % 21;
            const int ky = py + j / 3 - 1, kx = px + j % 3 - 1;
            float s = 0.0f;
            if (ky >= 0 && ky < KGRID && kx >= 0 && kx < KGRID) {
                #pragma unroll
                for (int dy = -1; dy <= 1; ++dy)
                    #pragma unroll
                    for (int dx = -1; dx <= 1; ++dx) {
                        const int cy = ky + dy, cx = kx + dx;
                        if (cy >= 0 && cy < KGRID && cx >= 0 && cx < KGRID) {
                            const int jj = (ky - cy + 1) * 3 + (kx - cx + 1);
                            s += src[((b * KK + cy * KGRID + cx) * 9 + jj) * 21 + c];
                        }
                    }
            }
            raw_s[t] = s;
        }
        __syncthreads();
        if (t < 9 * CC) {
            const int j = t / CC, c = t % CC;
            mean_s[t] = raw_s[j * 21 + c] / fmaxf(raw_s[j * 21 + 20], 1e-12f);
        }
    }
    __syncthreads();
    if (t < 9) {
        float s = 0.0f;
        #pragma unroll
        for (int c = 0; c < CC; ++c) { const float m = mean_s[t * CC + c]; s += m * m; }
        msq_s[t] = s;
    }
    __syncthreads();

    // -------- E-step: one pixel per thread --------
    // softmax(-dist) invariant to ||f||^2: p[j] ∝ exp(2*dot_j - msq_j).
    const int r = t >> 4, cc2 = t & 15;
    const int n = (py * CELLSZ + r) * HH + px * CELLSZ + cc2;
    const float4* fp = reinterpret_cast<const float4*>(feat + (size_t)(b * NN + n) * CC);
    float4 fv0 = fp[0], fv1 = fp[1], fv2 = fp[2], fv3 = fp[3], fv4 = fp[4];

    float s[9];
    float smax = -1e30f;
    #pragma unroll
    for (int j = 0; j < 9; ++j) {
        const int ky = py + j / 3 - 1, kx = px + j % 3 - 1;
        if (ky >= 0 && ky < KGRID && kx >= 0 && kx < KGRID) {
            const float4* mr = reinterpret_cast<const float4*>(mean_s + j * CC);
            float dot = 0.0f;
            float4 m;
            m = mr[0]; dot = fmaf(fv0.x,m.x,fmaf(fv0.y,m.y,fmaf(fv0.z,m.z,fmaf(fv0.w,m.w,dot))));
            m = mr[1]; dot = fmaf(fv1.x,m.x,fmaf(fv1.y,m.y,fmaf(fv1.z,m.z,fmaf(fv1.w,m.w,dot))));
            m = mr[2]; dot = fmaf(fv2.x,m.x,fmaf(fv2.y,m.y,fmaf(fv2.z,m.z,fmaf(fv2.w,m.w,dot))));
            m = mr[3]; dot = fmaf(fv3.x,m.x,fmaf(fv3.y,m.y,fmaf(fv3.z,m.z,fmaf(fv3.w,m.w,dot))));
            m = mr[4]; dot = fmaf(fv4.x,m.x,fmaf(fv4.y,m.y,fmaf(fv4.z,m.z,fmaf(fv4.w,m.w,dot))));
            s[j] = 2.0f * dot - msq_s[j];
            smax = fmaxf(smax, s[j]);
        } else {
            s[j] = -1e30f;
        }
    }
    float p[9], denom = 0.0f;
    #pragma unroll
    for (int j = 0; j < 9; ++j) {
        p[j] = (s[j] > -1e29f) ? __expf(s[j] - smax) : 0.0f;
        denom += p[j];
    }
    const float inv = 1.0f / denom;   // denom >= 1 (argmax contributes exp(0)=1)
    #pragma unroll
    for (int j = 0; j < 9; ++j) p_s[j * PS + t] = p[j] * inv;
    f_s[ 0 * PS + t] = fv0.x; f_s[ 1 * PS + t] = fv0.y; f_s[ 2 * PS + t] = fv0.z; f_s[ 3 * PS + t] = fv0.w;
    f_s[ 4 * PS + t] = fv1.x; f_s[ 5 * PS + t] = fv1.y; f_s[ 6 * PS + t] = fv1.z; f_s[ 7 * PS + t] = fv1.w;
    f_s[ 8 * PS + t] = fv2.x; f_s[ 9 * PS + t] = fv2.y; f_s[10 * PS + t] = fv2.z; f_s[11 * PS + t] = fv2.w;
    f_s[12 * PS + t] = fv3.x; f_s[13 * PS + t] = fv3.y; f_s[14 * PS + t] = fv3.z; f_s[15 * PS + t] = fv3.w;
    f_s[16 * PS + t] = fv4.x; f_s[17 * PS + t] = fv4.y; f_s[18 * PS + t] = fv4.z; f_s[19 * PS + t] = fv4.w;
    __syncthreads();

    // -------- M-step (tiled, float2-paired): 9 tiles of 3x7 (j,c),
    // 16 lanes/tile, each lane handles 2 adjacent pixels per iter (8 iters).
    // LDS.64 at even indices: rows are even-based (PS even) -> 8B aligned,
    // lanes cover 32 contiguous words per row -> conflict-free.
    float* __restrict__ dst = (mode == 1) ? g_partB : g_partA;
    if (t < 160) {
        const int tile = (t < 144) ? (t >> 4) : 8;  // lanes 16..31 of warp 4 duplicate tile 8
        const int g = t & 15;
        const int j0 = (tile / 3) * 3;
        const int c0 = (tile % 3) * 7;

        float acc[21];
        #pragma unroll
        for (int o = 0; o < 21; ++o) acc[o] = 0.0f;

        #pragma unroll 2
        for (int ii = 0; ii < 8; ++ii) {
            const int pix = ii * 32 + 2 * g;
            const float2 pj0 = *reinterpret_cast<const float2*>(&p_s[(j0 + 0) * PS + pix]);
            const float2 pj1 = *reinterpret_cast<const float2*>(&p_s[(j0 + 1) * PS + pix]);
            const float2 pj2 = *reinterpret_cast<const float2*>(&p_s[(j0 + 2) * PS + pix]);
            float2 fc[7];
            #pragma unroll
            for (int cc = 0; cc < 7; ++cc) {
                const int c = c0 + cc;
                fc[cc] = (c < CC) ? *reinterpret_cast<const float2*>(&f_s[c * PS + pix])
                                  : make_float2(1.0f, 1.0f);
            }
            #pragma unroll
            for (int cc = 0; cc < 7; ++cc) {
                acc[cc]      = fmaf(pj0.x, fc[cc].x, fmaf(pj0.y, fc[cc].y, acc[cc]));
                acc[7 + cc]  = fmaf(pj1.x, fc[cc].x, fmaf(pj1.y, fc[cc].y, acc[7 + cc]));
                acc[14 + cc] = fmaf(pj2.x, fc[cc].x, fmaf(pj2.y, fc[cc].y, acc[14 + cc]));
            }
        }
        // half-warp butterfly (offsets < 16 stay within the 16-lane group)
        #pragma unroll
        for (int o = 0; o < 21; ++o) {
            #pragma unroll
            for (int off = 8; off >= 1; off >>= 1)
                acc[o] += __shfl_xor_sync(0xffffffffu, acc[o], off);
        }
        if (t < 144) {
            const int base = ((b * KK + cell) * 9 + j0) * 21 + c0;
            {
                const int jj = g / 7, cc = g % 7;
                dst[base + jj * 21 + cc] = acc[g];
            }
            if (g < 5) {
                const int o = g + 16;
                const int jj = o / 7, cc = o % 7;
                dst[base + jj * 21 + cc] = acc[o];
            }
        }
    }
}

// ---------------------------------------------------------------------------
// FINAL: finalize mean from g_partA, E-step, expand to dense [B,N,K] output.
// grid=(K,B), 256 threads.
// ---------------------------------------------------------------------------
__global__ __launch_bounds__(256) void ssn_final(const float* __restrict__ feat,
                                                 float* __restrict__ out) {
    __shared__ float p_s[256 * 9];                      // p_s[pix][j]
    __shared__ __align__(16) float mean_s[9 * CC];
    __shared__ float msq_s[9];
    __shared__ float raw_s[9 * 21 + 3];

    const int b = blockIdx.y, cell = blockIdx.x, t = threadIdx.x;
    const int py = cell >> 4, px = cell & 15;

    // mean finalize from g_partA
    if (t < 9 * 21) {
        const int j = t / 21, c = t % 21;
        const int ky = py + j / 3 - 1, kx = px + j % 3 - 1;
        float s = 0.0f;
        if (ky >= 0 && ky < KGRID && kx >= 0 && kx < KGRID) {
            #pragma unroll
            for (int dy = -1; dy <= 1; ++dy)
                #pragma unroll
                for (int dx = -1; dx <= 1; ++dx) {
                    const int cy = ky + dy, cx = kx + dx;
                    if (cy >= 0 && cy < KGRID && cx >= 0 && cx < KGRID) {
                        const int jj = (ky - cy + 1) * 3 + (kx - cx + 1);
                        s += g_partA[((b * KK + cy * KGRID + cx) * 9 + jj) * 21 + c];
                    }
                }
        }
        raw_s[t] = s;
    }
    __syncthreads();
    if (t < 9 * CC) {
        const int j = t / CC, c = t % CC;
        mean_s[t] = raw_s[j * 21 + c] / fmaxf(raw_s[j * 21 + 20], 1e-12f);
    }
    __syncthreads();
    if (t < 9) {
        float s = 0.0f;
        #pragma unroll
        for (int c = 0; c < CC; ++c) { const float m = mean_s[t * CC + c]; s += m * m; }
        msq_s[t] = s;
    }
    __syncthreads();

    // E-step for this thread's pixel
    const int r = t >> 4, cc2 = t & 15;
    const int n = (py * CELLSZ + r) * HH + px * CELLSZ + cc2;
    const float4* fp = reinterpret_cast<const float4*>(feat + (size_t)(b * NN + n) * CC);
    float4 fv0 = fp[0], fv1 = fp[1], fv2 = fp[2], fv3 = fp[3], fv4 = fp[4];

    float s[9];
    float smax = -1e30f;
    #pragma unroll
    for (int j = 0; j < 9; ++j) {
        const int ky = py + j / 3 - 1, kx = px + j % 3 - 1;
        if (ky >= 0 && ky < KGRID && kx >= 0 && kx < KGRID) {
            const float4* mr = reinterpret_cast<const float4*>(mean_s + j * CC);
            float dot = 0.0f;
            float4 m;
            m = mr[0]; dot = fmaf(fv0.x,m.x,fmaf(fv0.y,m.y,fmaf(fv0.z,m.z,fmaf(fv0.w,m.w,dot))));
            m = mr[1]; dot = fmaf(fv1.x,m.x,fmaf(fv1.y,m.y,fmaf(fv1.z,m.z,fmaf(fv1.w,m.w,dot))));
            m = mr[2]; dot = fmaf(fv2.x,m.x,fmaf(fv2.y,m.y,fmaf(fv2.z,m.z,fmaf(fv2.w,m.w,dot))));
            m = mr[3]; dot = fmaf(fv3.x,m.x,fmaf(fv3.y,m.y,fmaf(fv3.z,m.z,fmaf(fv3.w,m.w,dot))));
            m = mr[4]; dot = fmaf(fv4.x,m.x,fmaf(fv4.y,m.y,fmaf(fv4.z,m.z,fmaf(fv4.w,m.w,dot))));
            s[j] = 2.0f * dot - msq_s[j];
            smax = fmaxf(smax, s[j]);
        } else {
            s[j] = -1e30f;
        }
    }
    float p[9], denom = 0.0f;
    #pragma unroll
    for (int j = 0; j < 9; ++j) {
        p[j] = (s[j] > -1e29f) ? __expf(s[j] - smax) : 0.0f;
        denom += p[j];
    }
    const float inv = 1.0f / denom;
    #pragma unroll
    for (int j = 0; j < 9; ++j) p_s[t * 9 + j] = p[j] * inv;
    __syncthreads();

    // Dense expansion: 64 iterations x (4 pixels x 64 float4s) = 256 pixels x 256 k
    const int sub = t >> 6;        // which of the 4 pixels this thread serves
    const int kq  = t & 63;        // float4 index within the k-row
    const int k0  = kq * 4;
    const int gy  = k0 >> 4;       // constant across the float4 (k0 % 16 <= 12)
    const int dy  = gy - py;
    const bool rowok = (dy >= -1 && dy <= 1);
    const int jbase = (dy + 1) * 3;
    const int gx0 = k0 & 15;

    for (int it = 0; it < 64; ++it) {
        const int pix = it * 4 + sub;
        const int rr = pix >> 4, cpx = pix & 15;
        const int n2 = (py * CELLSZ + rr) * HH + px * CELLSZ + cpx;
        const float* pr = &p_s[pix * 9];
        float4 v;
        {
            const int dx = gx0 + 0 - px;
            v.x = (rowok && dx >= -1 && dx <= 1) ? pr[jbase + dx + 1] : 0.0f;
        }
        {
            const int dx = gx0 + 1 - px;
            v.y = (rowok && dx >= -1 && dx <= 1) ? pr[jbase + dx + 1] : 0.0f;
        }
        {
            const int dx = gx0 + 2 - px;
            v.z = (rowok && dx >= -1 && dx <= 1) ? pr[jbase + dx + 1] : 0.0f;
        }
        {
            const int dx = gx0 + 3 - px;
            v.w = (rowok && dx >= -1 && dx <= 1) ? pr[jbase + dx + 1] : 0.0f;
        }
        reinterpret_cast<float4*>(out + (size_t)(b * NN + n2) * KK)[kq] = v;
    }
}

// ---------------------------------------------------------------------------
extern "C" void kernel_launch(void* const* d_in, const int* in_sizes, int n_in,
                              void* d_out, int out_size) {
    const float* feat = (const float*)d_in[0];
    float* out = (float*)d_out;
    (void)in_sizes; (void)n_in; (void)out_size;

    dim3 grid(KK, BN);

    ssn_init_mean<<<grid, 256>>>(feat);
    ssn_em_iter<<<grid, 256>>>(feat, 0);
    for (int i = 0; i < 4; ++i) {
        ssn_em_iter<<<grid, 256>>>(feat, 1);
        ssn_em_iter<<<grid, 256>>>(feat, 2);
    }
    ssn_final<<<grid, 256>>>(feat, out);
}